// round 1
// baseline (speedup 1.0000x reference)
#include <cuda_runtime.h>

// AbstractConv3D: 16 levels of dense R^3 grids, per-level 3x3x3 conv, Cin=Cout=16.
// Strategy: fp32 with packed fma.rn.f32x2 (2 FMA/issue), per-level weights staged
// in smem, 2 voxels per thread to amortize weight LDS, geometry hardcoded.

#define NLEV 16
#define TPB 128
#define VPB 256        // voxels per block (2 per thread)
#define TOTAL_N 1844282

__constant__ int c_res[NLEV] = {16,18,20,22,24,27,30,34,38,42,47,52,58,64,72,80};
__constant__ int c_off[NLEV] = {0,4096,9928,17928,28576,42400,62083,89083,128387,
                                183259,257347,361170,501778,696890,959034,1332282};
// cumulative block counts: ceil(R^3/256) per level
__constant__ int c_blk[NLEV+1] = {0,16,39,71,113,167,244,350,504,719,1009,1415,
                                  1965,2728,3752,5210,7210};

__device__ __forceinline__ unsigned long long pack2(float x) {
    unsigned long long r;
    unsigned u = __float_as_uint(x);
    asm("mov.b64 %0, {%1, %1};" : "=l"(r) : "r"(u));
    return r;
}

__device__ __forceinline__ unsigned long long pack2(float lo, float hi) {
    unsigned long long r;
    asm("mov.b64 %0, {%1, %2};" : "=l"(r) : "r"(__float_as_uint(lo)), "r"(__float_as_uint(hi)));
    return r;
}

__device__ __forceinline__ unsigned long long ffma2(unsigned long long a,
                                                    unsigned long long b,
                                                    unsigned long long c) {
    unsigned long long d;
    asm("fma.rn.f32x2 %0, %1, %2, %3;" : "=l"(d) : "l"(a), "l"(b), "l"(c));
    return d;
}

__device__ __forceinline__ void unpack2(unsigned long long v, float& lo, float& hi) {
    unsigned a, b;
    asm("mov.b64 {%0, %1}, %2;" : "=r"(a), "=r"(b) : "l"(v));
    lo = __uint_as_float(a);
    hi = __uint_as_float(b);
}

__global__ __launch_bounds__(TPB)
void conv3d_levels_kernel(const float* __restrict__ in,
                          const float* __restrict__ wgt,
                          const float* __restrict__ bias,
                          float* __restrict__ out) {
    const int blk = blockIdx.x;
    const int b = blockIdx.y;

    // level lookup (16-entry scan, unrolled, per-thread registers)
    int l = 0;
#pragma unroll
    for (int i = 1; i < NLEV; i++)
        if (blk >= c_blk[i]) l = i;

    const int lblk = blk - c_blk[l];
    const int R = c_res[l];
    const int off = c_off[l];
    const int R2 = R * R;
    const int R3 = R2 * R;

    // stage weights (27*16*16 = 6912 floats = 27.6KB) + bias into smem
    __shared__ float ws[6912];
    __shared__ float bs[16];
    {
        const float4* wg4 = (const float4*)(wgt + l * 6912);
        float4* ws4 = (float4*)ws;
#pragma unroll 4
        for (int i = threadIdx.x; i < 1728; i += TPB)
            ws4[i] = wg4[i];
        if (threadIdx.x < 16)
            bs[threadIdx.x] = bias[l * 16 + threadIdx.x];
    }
    __syncthreads();

    const int v0 = lblk * VPB + threadIdx.x;
    const int v1 = v0 + TPB;
    const bool ok0 = v0 < R3;
    const bool ok1 = v1 < R3;
    if (!ok0) return;   // v1 > v0, so nothing to do

    const int d0 = v0 / R2; int r0 = v0 - d0 * R2;
    const int h0 = r0 / R;  const int w0 = r0 - h0 * R;
    const int d1 = v1 / R2; int r1 = v1 - d1 * R2;
    const int h1 = r1 / R;  const int w1 = r1 - h1 * R;

    unsigned long long acc0[8], acc1[8];
#pragma unroll
    for (int k = 0; k < 8; k++) {
        unsigned long long bp = pack2(bs[2 * k], bs[2 * k + 1]);
        acc0[k] = bp;
        acc1[k] = bp;
    }

    const float* inB = in + ((size_t)b * TOTAL_N + off) * 16;

    for (int kd = 0; kd < 3; kd++) {
        const int dd0 = d0 + kd - 1;
        const int dd1 = d1 + kd - 1;
        for (int kh = 0; kh < 3; kh++) {
            const int hh0 = h0 + kh - 1;
            const int hh1 = h1 + kh - 1;
            for (int kw = 0; kw < 3; kw++) {
                const int ww0 = w0 + kw - 1;
                const int ww1 = w1 + kw - 1;
                const bool t0 = ((unsigned)dd0 < (unsigned)R) &&
                                ((unsigned)hh0 < (unsigned)R) &&
                                ((unsigned)ww0 < (unsigned)R);
                const bool t1 = ok1 &&
                                ((unsigned)dd1 < (unsigned)R) &&
                                ((unsigned)hh1 < (unsigned)R) &&
                                ((unsigned)ww1 < (unsigned)R);

                float x0v[16], x1v[16];
                if (t0) {
                    const float4* p = (const float4*)(inB + (size_t)((dd0 * R + hh0) * R + ww0) * 16);
#pragma unroll
                    for (int q = 0; q < 4; q++)
                        *(float4*)&x0v[4 * q] = __ldg(p + q);
                } else {
#pragma unroll
                    for (int i = 0; i < 16; i++) x0v[i] = 0.0f;
                }
                if (t1) {
                    const float4* p = (const float4*)(inB + (size_t)((dd1 * R + hh1) * R + ww1) * 16);
#pragma unroll
                    for (int q = 0; q < 4; q++)
                        *(float4*)&x1v[4 * q] = __ldg(p + q);
                } else {
#pragma unroll
                    for (int i = 0; i < 16; i++) x1v[i] = 0.0f;
                }

                const unsigned long long* wt =
                    (const unsigned long long*)(ws + ((kd * 3 + kh) * 3 + kw) * 256);
#pragma unroll
                for (int ci = 0; ci < 16; ci++) {
                    const unsigned long long a0 = pack2(x0v[ci]);
                    const unsigned long long a1 = pack2(x1v[ci]);
                    const unsigned long long* wr = wt + ci * 8;
#pragma unroll
                    for (int k = 0; k < 8; k++) {
                        const unsigned long long wv = wr[k];
                        acc0[k] = ffma2(a0, wv, acc0[k]);
                        acc1[k] = ffma2(a1, wv, acc1[k]);
                    }
                }
            }
        }
    }

    // write results
    {
        float o[16];
#pragma unroll
        for (int k = 0; k < 8; k++)
            unpack2(acc0[k], o[2 * k], o[2 * k + 1]);
        float4* po = (float4*)(out + ((size_t)b * TOTAL_N + off + v0) * 16);
#pragma unroll
        for (int q = 0; q < 4; q++)
            po[q] = *(float4*)&o[4 * q];
    }
    if (ok1) {
        float o[16];
#pragma unroll
        for (int k = 0; k < 8; k++)
            unpack2(acc1[k], o[2 * k], o[2 * k + 1]);
        float4* po = (float4*)(out + ((size_t)b * TOTAL_N + off + v1) * 16);
#pragma unroll
        for (int q = 0; q < 4; q++)
            po[q] = *(float4*)&o[4 * q];
    }
}

extern "C" void kernel_launch(void* const* d_in, const int* in_sizes, int n_in,
                              void* d_out, int out_size) {
    const float* in   = (const float*)d_in[0];
    const float* wgt  = (const float*)d_in[1];
    const float* bias = (const float*)d_in[2];
    float* out = (float*)d_out;

    dim3 grid(7210, 2);
    conv3d_levels_kernel<<<grid, TPB>>>(in, wgt, bias, out);
}

// round 3
// speedup vs baseline: 1.3927x; 1.3927x over previous
#include <cuda_runtime.h>

// AbstractConv3D: 16 levels of dense R^3 grids, 3x3x3 conv, Cin=Cout=16, B=2.
// R2 strategy: smem-tiled 8x8x8 output blocks, halo zero-filled (branch-free
// hot loop), 4 outputs/thread along w sharing LDS.128 weight broadcasts,
// packed fma.rn.f32x2 accumulation.

#define NLEV 16
#define TPB 128
#define TOTAL_N 1844282

typedef unsigned long long ull;

__constant__ int c_res[NLEV]  = {16,18,20,22,24,27,30,34,38,42,47,52,58,64,72,80};
__constant__ int c_off[NLEV]  = {0,4096,9928,17928,28576,42400,62083,89083,128387,
                                 183259,257347,361170,501778,696890,959034,1332282};
__constant__ int c_nt[NLEV]   = {2,3,3,3,3,4,4,5,5,6,6,7,8,8,9,10};   // ceil(R/8)
__constant__ int c_tblk[NLEV+1] = {0,8,35,62,89,116,180,244,369,494,710,926,
                                   1269,1781,2293,3022,4022};

// smem layout (floats): [0,6912) weights, [6912,6928) bias, [6928, ...) input tile
// input tile: 4 chunks x 1100 granules x 16B (10x10x10 voxels, row stride 11,
// plane stride 110 -> bank-spread for conflict-free LDS.128)
#define SMEM_FLOATS (6928 + 4*1100*4)

__device__ __forceinline__ ull pack2(float x) {
    ull r; unsigned u = __float_as_uint(x);
    asm("mov.b64 %0, {%1, %1};" : "=l"(r) : "r"(u));
    return r;
}
__device__ __forceinline__ ull pack2(float lo, float hi) {
    ull r;
    asm("mov.b64 %0, {%1, %2};" : "=l"(r) : "r"(__float_as_uint(lo)), "r"(__float_as_uint(hi)));
    return r;
}
__device__ __forceinline__ ull ffma2(ull a, ull b, ull c) {
    ull d;
    asm("fma.rn.f32x2 %0, %1, %2, %3;" : "=l"(d) : "l"(a), "l"(b), "l"(c));
    return d;
}
__device__ __forceinline__ void unpack2(ull v, float& lo, float& hi) {
    unsigned a, b;
    asm("mov.b64 {%0, %1}, %2;" : "=r"(a), "=r"(b) : "l"(v));
    lo = __uint_as_float(a); hi = __uint_as_float(b);
}

__global__ __launch_bounds__(TPB)
void conv3d_tile_kernel(const float* __restrict__ in,
                        const float* __restrict__ wgt,
                        const float* __restrict__ bias,
                        float* __restrict__ out) {
    extern __shared__ float smem[];
    float* ws = smem;              // 6912 floats
    float* bs = smem + 6912;       // 16 floats
    float4* in4 = (float4*)(smem + 6928);  // 4*1100 granules

    const int blk = blockIdx.x;
    const int b = blockIdx.y;
    const int tid = threadIdx.x;

    // level lookup
    int l = 0;
#pragma unroll
    for (int i = 1; i < NLEV; i++)
        if (blk >= c_tblk[i]) l = i;
    const int lblk = blk - c_tblk[l];
    const int R = c_res[l];
    const int off = c_off[l];
    const int nt = c_nt[l];

    // tile coords
    const int tz = lblk / (nt * nt);
    const int trem = lblk - tz * nt * nt;
    const int ty = trem / nt;
    const int tx = trem - ty * nt;

    // ---- stage weights + bias ----
    {
        const float4* wg4 = (const float4*)(wgt + l * 6912);
        float4* ws4 = (float4*)ws;
#pragma unroll 4
        for (int i = tid; i < 1728; i += TPB)
            ws4[i] = wg4[i];
        if (tid < 16)
            bs[tid] = bias[l * 16 + tid];
    }

    // ---- stage input tile 10x10x10 (halo zero-filled) ----
    {
        const int d0 = tz * 8 - 1, h0 = ty * 8 - 1, w0 = tx * 8 - 1;
        const float* inB = in + ((size_t)b * TOTAL_N + off) * 16;
        for (int i = tid; i < 1000; i += TPB) {
            int dz = i / 100; int r = i - dz * 100;
            int hy = r / 10;  int wx = r - hy * 10;
            int dd = d0 + dz, hh = h0 + hy, ww = w0 + wx;
            float4 v0 = {0,0,0,0}, v1 = {0,0,0,0}, v2 = {0,0,0,0}, v3 = {0,0,0,0};
            if (((unsigned)dd < (unsigned)R) & ((unsigned)hh < (unsigned)R) &
                ((unsigned)ww < (unsigned)R)) {
                const float4* p = (const float4*)(inB + (size_t)((dd * R + hh) * R + ww) * 16);
                v0 = __ldg(p + 0); v1 = __ldg(p + 1); v2 = __ldg(p + 2); v3 = __ldg(p + 3);
            }
            int g = dz * 110 + hy * 11 + wx;
            in4[g] = v0;
            in4[1100 + g] = v1;
            in4[2200 + g] = v2;
            in4[3300 + g] = v3;
        }
    }
    __syncthreads();

    // ---- thread output mapping: 4 outputs along w ----
    const int wq = tid & 1;            // w group (0 or 1): outputs w = 4*wq .. +3
    const int hy_t = (tid >> 1) & 7;
    const int dz_t = tid >> 4;

    ull acc[4][8];
    {
        ull bp[8];
#pragma unroll
        for (int k = 0; k < 8; k++) bp[k] = pack2(bs[2 * k], bs[2 * k + 1]);
#pragma unroll
        for (int o = 0; o < 4; o++)
#pragma unroll
            for (int k = 0; k < 8; k++) acc[o][k] = bp[k];
    }

    // ---- main loop over 27 taps (branch-free; halo is zero) ----
    for (int tap = 0; tap < 27; tap++) {
        int kd = tap / 9; int r = tap - kd * 9;
        int kh = r / 3;   int kw = r - kh * 3;
        const int gbase = (dz_t + kd) * 110 + (hy_t + kh) * 11 + (wq * 4 + kw);
        const ulonglong2* wp2 = (const ulonglong2*)(ws + tap * 256);
#pragma unroll
        for (int q = 0; q < 4; q++) {
            float4 x0 = in4[q * 1100 + gbase + 0];
            float4 x1 = in4[q * 1100 + gbase + 1];
            float4 x2 = in4[q * 1100 + gbase + 2];
            float4 x3 = in4[q * 1100 + gbase + 3];
            const float* xf0 = (const float*)&x0;
            const float* xf1 = (const float*)&x1;
            const float* xf2 = (const float*)&x2;
            const float* xf3 = (const float*)&x3;
#pragma unroll
            for (int cl = 0; cl < 4; cl++) {
                const int ci = q * 4 + cl;
                ull a0 = pack2(xf0[cl]);
                ull a1 = pack2(xf1[cl]);
                ull a2 = pack2(xf2[cl]);
                ull a3 = pack2(xf3[cl]);
#pragma unroll
                for (int kp = 0; kp < 4; kp++) {
                    ulonglong2 wv = wp2[ci * 4 + kp];   // LDS.128 broadcast
                    acc[0][2*kp]   = ffma2(a0, wv.x, acc[0][2*kp]);
                    acc[1][2*kp]   = ffma2(a1, wv.x, acc[1][2*kp]);
                    acc[2][2*kp]   = ffma2(a2, wv.x, acc[2][2*kp]);
                    acc[3][2*kp]   = ffma2(a3, wv.x, acc[3][2*kp]);
                    acc[0][2*kp+1] = ffma2(a0, wv.y, acc[0][2*kp+1]);
                    acc[1][2*kp+1] = ffma2(a1, wv.y, acc[1][2*kp+1]);
                    acc[2][2*kp+1] = ffma2(a2, wv.y, acc[2][2*kp+1]);
                    acc[3][2*kp+1] = ffma2(a3, wv.y, acc[3][2*kp+1]);
                }
            }
        }
    }

    // ---- store ----
    const int od = tz * 8 + dz_t;
    const int oh = ty * 8 + hy_t;
    const int ow0 = tx * 8 + wq * 4;
    if (od < R && oh < R) {
        float* outB = out + ((size_t)b * TOTAL_N + off) * 16;
#pragma unroll
        for (int o = 0; o < 4; o++) {
            if (ow0 + o < R) {
                float ov[16];
#pragma unroll
                for (int k = 0; k < 8; k++)
                    unpack2(acc[o][k], ov[2 * k], ov[2 * k + 1]);
                float4* po = (float4*)(outB + (size_t)((od * R + oh) * R + ow0 + o) * 16);
#pragma unroll
                for (int q = 0; q < 4; q++)
                    po[q] = *(float4*)&ov[4 * q];
            }
        }
    }
}

extern "C" void kernel_launch(void* const* d_in, const int* in_sizes, int n_in,
                              void* d_out, int out_size) {
    const float* in   = (const float*)d_in[0];
    const float* wgt  = (const float*)d_in[1];
    const float* bias = (const float*)d_in[2];
    float* out = (float*)d_out;

    static int configured = 0;
    if (!configured) {
        cudaFuncSetAttribute(conv3d_tile_kernel,
                             cudaFuncAttributeMaxDynamicSharedMemorySize,
                             SMEM_FLOATS * 4);
        configured = 1;
    }

    dim3 grid(4022, 2);
    conv3d_tile_kernel<<<grid, TPB, SMEM_FLOATS * 4>>>(in, wgt, bias, out);
}

// round 6
// speedup vs baseline: 2.5368x; 1.8215x over previous
#include <cuda_runtime.h>

// AbstractConv3D: 16 levels, dense R^3 grids, 3x3x3 conv, Cin=Cout=16, B=2.
// R4: tensor cores via mma.sync.m16n8k8 tf32 (HMMA fallback path; tcgen05 PTX
// rejected by compute_103 toolchain). 8x8x8 tile, 10^3 halo in smem chunk-major
// layout (conflict-free A-fragment LDS), weights tf32 in smem, bias in accum init.

#define NLEV 16
#define TPB 128
#define TOTAL_N 1844282

__constant__ int c_res[NLEV]  = {16,18,20,22,24,27,30,34,38,42,47,52,58,64,72,80};
__constant__ int c_off[NLEV]  = {0,4096,9928,17928,28576,42400,62083,89083,128387,
                                 183259,257347,361170,501778,696890,959034,1332282};
__constant__ int c_nt[NLEV]   = {2,3,3,3,3,4,4,5,5,6,6,7,8,8,9,10};   // ceil(R/8)
__constant__ int c_tblk[NLEV+1] = {0,8,35,62,89,116,180,244,369,494,710,926,
                                   1269,1781,2293,3022,4022};

// smem (bytes): [0,27648) weights tf32 [tap][ci][co], [27648,27712) bias f32,
// [27712, 27712+70400) input tile: 4 ci-chunks x 1100 granules x 16B
// granule g = dz*110 + hy*11 + wx  (10x10x10 voxels)
#define SM_W    0
#define SM_BIAS 27648
#define SM_A    27712
#define SM_TOTAL (27712 + 70400)

__device__ __forceinline__ unsigned smem_u32(const void* p) {
    unsigned a;
    asm("{ .reg .u64 t; cvta.to.shared.u64 t, %1; cvt.u32.u64 %0, t; }"
        : "=r"(a) : "l"(p));
    return a;
}
__device__ __forceinline__ unsigned f2tf32(float x) {
    unsigned u;
    asm("cvt.rna.tf32.f32 %0, %1;" : "=r"(u) : "f"(x));
    return u;
}
__device__ __forceinline__ unsigned lds32(unsigned a) {
    unsigned v;
    asm volatile("ld.shared.b32 %0, [%1];" : "=r"(v) : "r"(a));
    return v;
}
__device__ __forceinline__ void mma_tf32(float* c,
                                         unsigned a0, unsigned a1, unsigned a2, unsigned a3,
                                         unsigned b0, unsigned b1) {
    asm volatile(
        "mma.sync.aligned.m16n8k8.row.col.f32.tf32.tf32.f32 "
        "{%0,%1,%2,%3}, {%4,%5,%6,%7}, {%8,%9}, {%0,%1,%2,%3};"
        : "+f"(c[0]), "+f"(c[1]), "+f"(c[2]), "+f"(c[3])
        : "r"(a0), "r"(a1), "r"(a2), "r"(a3), "r"(b0), "r"(b1));
}

__global__ __launch_bounds__(TPB)
void conv3d_mma_kernel(const float* __restrict__ in,
                       const float* __restrict__ wgt,
                       const float* __restrict__ bias,
                       float* __restrict__ out) {
    extern __shared__ char smem[];
    const unsigned sbase = smem_u32(smem);
    const int tid = threadIdx.x;
    const int wid = tid >> 5;
    const int lane = tid & 31;
    const int r4 = lane >> 2;      // fragment "group" (0..7)
    const int c4 = lane & 3;       // thread-in-group (0..3)
    const int b = blockIdx.y;
    const int blk = blockIdx.x;

    // level + tile decode
    int l = 0;
#pragma unroll
    for (int i = 1; i < NLEV; i++)
        if (blk >= c_tblk[i]) l = i;
    const int lblk = blk - c_tblk[l];
    const int R = c_res[l];
    const int off = c_off[l];
    const int nt = c_nt[l];
    const int tz = lblk / (nt * nt);
    const int trem = lblk - tz * nt * nt;
    const int ty = trem / nt;
    const int tx = trem - ty * nt;

    // ---- stage weights (tf32) + bias ----
    {
        const float4* wg4 = (const float4*)(wgt + l * 6912);
#pragma unroll 4
        for (int i = tid; i < 1728; i += TPB) {
            float4 v = __ldg(wg4 + i);
            unsigned u0 = f2tf32(v.x), u1 = f2tf32(v.y),
                     u2 = f2tf32(v.z), u3 = f2tf32(v.w);
            asm volatile("st.shared.v4.b32 [%0], {%1,%2,%3,%4};"
                         :: "r"(sbase + SM_W + i * 16),
                            "r"(u0), "r"(u1), "r"(u2), "r"(u3) : "memory");
        }
        if (tid < 16)
            *(float*)(smem + SM_BIAS + tid * 4) = bias[l * 16 + tid];
    }

    // ---- stage input tile 10x10x10 (tf32, halo zero, chunk-major) ----
    {
        const int d0 = tz * 8 - 1, h0 = ty * 8 - 1, w0 = tx * 8 - 1;
        const float* inB = in + ((size_t)b * TOTAL_N + off) * 16;
        for (int i = tid; i < 1000; i += TPB) {
            int dz = i / 100; int r = i - dz * 100;
            int hy = r / 10;  int wx = r - hy * 10;
            int dd = d0 + dz, hh = h0 + hy, ww = w0 + wx;
            unsigned u[16];
#pragma unroll
            for (int q = 0; q < 16; q++) u[q] = 0u;
            if (((unsigned)dd < (unsigned)R) & ((unsigned)hh < (unsigned)R) &
                ((unsigned)ww < (unsigned)R)) {
                const float4* p = (const float4*)(inB + (size_t)((dd * R + hh) * R + ww) * 16);
#pragma unroll
                for (int q = 0; q < 4; q++) {
                    float4 v = __ldg(p + q);
                    u[4 * q + 0] = f2tf32(v.x);
                    u[4 * q + 1] = f2tf32(v.y);
                    u[4 * q + 2] = f2tf32(v.z);
                    u[4 * q + 3] = f2tf32(v.w);
                }
            }
            const unsigned g16 = sbase + SM_A + (unsigned)(dz * 110 + hy * 11 + wx) * 16;
#pragma unroll
            for (int c = 0; c < 4; c++) {
                asm volatile("st.shared.v4.b32 [%0], {%1,%2,%3,%4};"
                             :: "r"(g16 + c * 17600),
                                "r"(u[4*c]), "r"(u[4*c+1]), "r"(u[4*c+2]), "r"(u[4*c+3])
                             : "memory");
            }
        }
    }
    __syncthreads();

    // ---- accumulators: [mblk j][nhalf][4], bias-initialized ----
    // c-frag: c0 row=r4 col=2*c4, c1 col+1, c2 row+8, c3 row+8 col+1
    float acc[8][2][4];
    {
        const float* bs = (const float*)(smem + SM_BIAS);
        float b00 = bs[2 * c4], b01 = bs[2 * c4 + 1];
        float b10 = bs[2 * c4 + 8], b11 = bs[2 * c4 + 9];
#pragma unroll
        for (int j = 0; j < 8; j++) {
            acc[j][0][0] = b00; acc[j][0][1] = b01; acc[j][0][2] = b00; acc[j][0][3] = b01;
            acc[j][1][0] = b10; acc[j][1][1] = b11; acc[j][1][2] = b10; acc[j][1][3] = b11;
        }
    }

    const unsigned aBase = sbase + SM_A + r4 * 16 + c4 * 4;   // A-frag thread offset
    const unsigned wBase = sbase + SM_W + c4 * 64 + r4 * 4;   // B-frag thread offset
    const int wid2 = wid * 2;

    // m-block j: d-plane = wid2 + (j>>2), h-pair = (j&3)
    // granule offset of j (relative): (j>>2)*110 + (j&3)*22
    // A-frag rows: a0/a2 at hl=0, a1/a3 at +11 granules (hl=1)

    for (int tap = 0; tap < 27; tap++) {
        const int kd = tap / 9;
        const int r9 = tap - kd * 9;
        const int kh = r9 / 3;
        const int kw = r9 - kh * 3;
        const unsigned base0 = (unsigned)((wid2 + kd) * 110 + kh * 11 + kw);

        // B fragments: wb[ks][nh][2]
        const unsigned wt = wBase + (unsigned)tap * 1024;
        unsigned wb[2][2][2];
#pragma unroll
        for (int ks = 0; ks < 2; ks++)
#pragma unroll
            for (int nh = 0; nh < 2; nh++) {
                wb[ks][nh][0] = lds32(wt + ks * 512 + nh * 32);
                wb[ks][nh][1] = lds32(wt + ks * 512 + nh * 32 + 256);
            }

        const unsigned aT = aBase + base0 * 16;
#pragma unroll
        for (int j = 0; j < 8; j++) {
            const unsigned ap = aT + (unsigned)(((j >> 2) * 110 + (j & 3) * 22) * 16);
            // ks = 0: chunks 0,1
            unsigned a0 = lds32(ap);
            unsigned a1 = lds32(ap + 176);
            unsigned a2 = lds32(ap + 17600);
            unsigned a3 = lds32(ap + 17776);
            mma_tf32(acc[j][0], a0, a1, a2, a3, wb[0][0][0], wb[0][0][1]);
            mma_tf32(acc[j][1], a0, a1, a2, a3, wb[0][1][0], wb[0][1][1]);
            // ks = 1: chunks 2,3
            unsigned e0 = lds32(ap + 35200);
            unsigned e1 = lds32(ap + 35376);
            unsigned e2 = lds32(ap + 52800);
            unsigned e3 = lds32(ap + 52976);
            mma_tf32(acc[j][0], e0, e1, e2, e3, wb[1][0][0], wb[1][0][1]);
            mma_tf32(acc[j][1], e0, e1, e2, e3, wb[1][1][0], wb[1][1][1]);
        }
    }

    // ---- epilogue ----
    // thread writes voxels (oh = ty*8 + (j&3)*2 + hl, ow = tx*8 + r4),
    // cols co = 2*c4 + nh*8 (+1)
    const int ow = tx * 8 + r4;
    float* outB = out + ((size_t)b * TOTAL_N + off) * 16;
    if (ow < R) {
#pragma unroll
        for (int j = 0; j < 8; j++) {
            const int od = tz * 8 + wid2 + (j >> 2);
            if (od >= R) continue;
#pragma unroll
            for (int hl = 0; hl < 2; hl++) {
                const int oh = ty * 8 + (j & 3) * 2 + hl;
                if (oh >= R) continue;
                float* po = outB + (size_t)((od * R + oh) * R + ow) * 16;
                float2 v0 = make_float2(acc[j][0][hl * 2], acc[j][0][hl * 2 + 1]);
                float2 v1 = make_float2(acc[j][1][hl * 2], acc[j][1][hl * 2 + 1]);
                *(float2*)(po + 2 * c4) = v0;
                *(float2*)(po + 2 * c4 + 8) = v1;
            }
        }
    }
}

extern "C" void kernel_launch(void* const* d_in, const int* in_sizes, int n_in,
                              void* d_out, int out_size) {
    const float* in   = (const float*)d_in[0];
    const float* wgt  = (const float*)d_in[1];
    const float* bias = (const float*)d_in[2];
    float* out = (float*)d_out;

    static int configured = 0;
    if (!configured) {
        cudaFuncSetAttribute(conv3d_mma_kernel,
                             cudaFuncAttributeMaxDynamicSharedMemorySize,
                             SM_TOTAL);
        configured = 1;
    }

    dim3 grid(4022, 2);
    conv3d_mma_kernel<<<grid, TPB, SM_TOTAL>>>(in, wgt, bias, out);
}

// round 9
// speedup vs baseline: 3.2285x; 1.2726x over previous
#include <cuda_runtime.h>

// AbstractConv3D: 16 levels, dense R^3 grids, 3x3x3 conv, Cin=Cout=16, B=2.
// R7: mma.sync m16n8k8 tf32. 8x8x8 tile, 10^3 halo in smem. 256 threads,
// one d-plane per warp. Paired-chunk A layout (ci perm [0,4,1,5,2,6,3,7] per
// 32B granule) -> A-fragment pairs via single LDS.64. Frag-major weights in
// smem -> conflict-free LDS.64 B loads.

#define NLEV 16
#define TPB 256
#define TOTAL_N 1844282

__constant__ int c_res[NLEV]  = {16,18,20,22,24,27,30,34,38,42,47,52,58,64,72,80};
__constant__ int c_off[NLEV]  = {0,4096,9928,17928,28576,42400,62083,89083,128387,
                                 183259,257347,361170,501778,696890,959034,1332282};
__constant__ int c_nt[NLEV]   = {2,3,3,3,3,4,4,5,5,6,6,7,8,8,9,10};   // ceil(R/8)
__constant__ int c_tblk[NLEV+1] = {0,8,35,62,89,116,180,244,369,494,710,926,
                                   1269,1781,2293,3022,4022};

// smem (bytes):
// [0,27648)        weights frag-major: [tap][f=ks*2+nh][lane][2 regs] tf32
// [27648,27712)    bias f32
// [27712,98112)    input tile: 2 regions x 1100 granules x 32B
//   region0 = ci pairs (c,c+4) c<4 ; region1 = ci pairs (c+8,c+12)
//   granule g = dz*110 + hy*11 + wx  (10x10x10 voxels)
#define SM_W    0
#define SM_BIAS 27648
#define SM_A    27712
#define SM_REG2 35200        // byte offset between the two ci-pair regions
#define SM_TOTAL 98112

__device__ __forceinline__ unsigned smem_u32(const void* p) {
    unsigned a;
    asm("{ .reg .u64 t; cvta.to.shared.u64 t, %1; cvt.u32.u64 %0, t; }"
        : "=r"(a) : "l"(p));
    return a;
}
__device__ __forceinline__ unsigned f2tf32(float x) {
    unsigned u;
    asm("cvt.rna.tf32.f32 %0, %1;" : "=r"(u) : "f"(x));
    return u;
}
__device__ __forceinline__ uint2 lds64(unsigned a) {
    uint2 v;
    asm volatile("ld.shared.v2.b32 {%0,%1}, [%2];" : "=r"(v.x), "=r"(v.y) : "r"(a));
    return v;
}
__device__ __forceinline__ void mma_tf32(float* c,
                                         unsigned a0, unsigned a1, unsigned a2, unsigned a3,
                                         unsigned b0, unsigned b1) {
    asm volatile(
        "mma.sync.aligned.m16n8k8.row.col.f32.tf32.tf32.f32 "
        "{%0,%1,%2,%3}, {%4,%5,%6,%7}, {%8,%9}, {%0,%1,%2,%3};"
        : "+f"(c[0]), "+f"(c[1]), "+f"(c[2]), "+f"(c[3])
        : "r"(a0), "r"(a1), "r"(a2), "r"(a3), "r"(b0), "r"(b1));
}

__global__ __launch_bounds__(TPB)
void conv3d_mma2_kernel(const float* __restrict__ in,
                        const float* __restrict__ wgt,
                        const float* __restrict__ bias,
                        float* __restrict__ out) {
    extern __shared__ char smem[];
    const unsigned sbase = smem_u32(smem);
    const int tid = threadIdx.x;
    const int wid = tid >> 5;      // warp = d-plane (0..7)
    const int lane = tid & 31;
    const int r4 = lane >> 2;      // w index / B co row (0..7)
    const int c4 = lane & 3;       // k-group (0..3)
    const int b = blockIdx.y;
    const int blk = blockIdx.x;

    // level + tile decode
    int l = 0;
#pragma unroll
    for (int i = 1; i < NLEV; i++)
        if (blk >= c_tblk[i]) l = i;
    const int lblk = blk - c_tblk[l];
    const int R = c_res[l];
    const int off = c_off[l];
    const int nt = c_nt[l];
    const int tz = lblk / (nt * nt);
    const int trem = lblk - tz * nt * nt;
    const int ty = trem / nt;
    const int tx = trem - ty * nt;

    // ---- stage weights frag-major ----
    // item (tap, f): f = ks*2+nh. Lane holds regs (ci=8ks+c4, co=8nh+r4) and (ci+4, co).
    {
        const float* wl = wgt + l * 6912;
        for (int it = wid; it < 108; it += 8) {
            const int tap = it >> 2;
            const int f = it & 3;
            const int ks = f >> 1;
            const int nh = f & 1;
            const int ci = 8 * ks + c4;
            const int co = 8 * nh + r4;
            const unsigned u0 = f2tf32(__ldg(wl + tap * 256 + ci * 16 + co));
            const unsigned u1 = f2tf32(__ldg(wl + tap * 256 + (ci + 4) * 16 + co));
            asm volatile("st.shared.v2.b32 [%0], {%1,%2};"
                         :: "r"(sbase + SM_W + (unsigned)(tap * 1024 + f * 256 + lane * 8)),
                            "r"(u0), "r"(u1) : "memory");
        }
        if (tid < 16)
            *(float*)(smem + SM_BIAS + tid * 4) = bias[l * 16 + tid];
    }

    // ---- stage input tile 10x10x10 (tf32, halo zero, paired-chunk layout) ----
    {
        const int d0 = tz * 8 - 1, h0 = ty * 8 - 1, w0 = tx * 8 - 1;
        const float* inB = in + ((size_t)b * TOTAL_N + off) * 16;
        for (int i = tid; i < 1000; i += TPB) {
            int dz = i / 100; int r = i - dz * 100;
            int hy = r / 10;  int wx = r - hy * 10;
            int dd = d0 + dz, hh = h0 + hy, ww = w0 + wx;
            unsigned u[16];
#pragma unroll
            for (int q = 0; q < 16; q++) u[q] = 0u;
            if (((unsigned)dd < (unsigned)R) & ((unsigned)hh < (unsigned)R) &
                ((unsigned)ww < (unsigned)R)) {
                const float4* p = (const float4*)(inB + (size_t)((dd * R + hh) * R + ww) * 16);
#pragma unroll
                for (int q = 0; q < 4; q++) {
                    float4 v = __ldg(p + q);
                    u[4 * q + 0] = f2tf32(v.x);
                    u[4 * q + 1] = f2tf32(v.y);
                    u[4 * q + 2] = f2tf32(v.z);
                    u[4 * q + 3] = f2tf32(v.w);
                }
            }
            const unsigned g32 = sbase + SM_A + (unsigned)(dz * 110 + hy * 11 + wx) * 32;
            // region0: ci [0,4,1,5] [2,6,3,7]
            asm volatile("st.shared.v4.b32 [%0], {%1,%2,%3,%4};"
                         :: "r"(g32), "r"(u[0]), "r"(u[4]), "r"(u[1]), "r"(u[5]) : "memory");
            asm volatile("st.shared.v4.b32 [%0], {%1,%2,%3,%4};"
                         :: "r"(g32 + 16), "r"(u[2]), "r"(u[6]), "r"(u[3]), "r"(u[7]) : "memory");
            // region1: ci [8,12,9,13] [10,14,11,15]
            asm volatile("st.shared.v4.b32 [%0], {%1,%2,%3,%4};"
                         :: "r"(g32 + SM_REG2), "r"(u[8]), "r"(u[12]), "r"(u[9]), "r"(u[13]) : "memory");
            asm volatile("st.shared.v4.b32 [%0], {%1,%2,%3,%4};"
                         :: "r"(g32 + SM_REG2 + 16), "r"(u[10]), "r"(u[14]), "r"(u[11]), "r"(u[15]) : "memory");
        }
    }
    __syncthreads();

    // ---- accumulators [h-pair j][nh][4], bias-initialized ----
    float acc[4][2][4];
    {
        const float* bs = (const float*)(smem + SM_BIAS);
        float b00 = bs[2 * c4], b01 = bs[2 * c4 + 1];
        float b10 = bs[2 * c4 + 8], b11 = bs[2 * c4 + 9];
#pragma unroll
        for (int j = 0; j < 4; j++) {
            acc[j][0][0] = b00; acc[j][0][1] = b01; acc[j][0][2] = b00; acc[j][0][3] = b01;
            acc[j][1][0] = b10; acc[j][1][1] = b11; acc[j][1][2] = b10; acc[j][1][3] = b11;
        }
    }

    const unsigned aBase = sbase + SM_A + (unsigned)(r4 * 32 + c4 * 8);
    const unsigned wB = sbase + SM_W + (unsigned)(lane * 8);

    for (int tap = 0; tap < 27; tap++) {
        const int kd = tap / 9;
        const int r9 = tap - kd * 9;
        const int kh = r9 / 3;
        const int kw = r9 - kh * 3;

        // B fragments: 4 conflict-free LDS.64
        const unsigned wt = wB + (unsigned)tap * 1024;
        const uint2 wb0 = lds64(wt);          // ks0 nh0
        const uint2 wb1 = lds64(wt + 256);    // ks0 nh1
        const uint2 wb2 = lds64(wt + 512);    // ks1 nh0
        const uint2 wb3 = lds64(wt + 768);    // ks1 nh1

        const unsigned gb = aBase + (unsigned)(((wid + kd) * 110 + kh * 11 + kw) * 32);
#pragma unroll
        for (int j = 0; j < 4; j++) {
            const unsigned ap = gb + (unsigned)(j * 704);   // 2 h-rows per j
            const uint2 a02 = lds64(ap);             // (a0, a2) ci pair, h row 0
            const uint2 a13 = lds64(ap + 352);       // (a1, a3) h row 1
            const uint2 e02 = lds64(ap + SM_REG2);
            const uint2 e13 = lds64(ap + SM_REG2 + 352);
            mma_tf32(acc[j][0], a02.x, a13.x, a02.y, a13.y, wb0.x, wb0.y);
            mma_tf32(acc[j][1], a02.x, a13.x, a02.y, a13.y, wb1.x, wb1.y);
            mma_tf32(acc[j][0], e02.x, e13.x, e02.y, e13.y, wb2.x, wb2.y);
            mma_tf32(acc[j][1], e02.x, e13.x, e02.y, e13.y, wb3.x, wb3.y);
        }
    }

    // ---- epilogue ----
    const int ow = tx * 8 + r4;
    const int od = tz * 8 + wid;
    float* outB = out + ((size_t)b * TOTAL_N + off) * 16;
    if (ow < R && od < R) {
#pragma unroll
        for (int j = 0; j < 4; j++) {
#pragma unroll
            for (int hl = 0; hl < 2; hl++) {
                const int oh = ty * 8 + j * 2 + hl;
                if (oh >= R) continue;
                float* po = outB + (size_t)((od * R + oh) * R + ow) * 16;
                *(float2*)(po + 2 * c4)     = make_float2(acc[j][0][hl * 2], acc[j][0][hl * 2 + 1]);
                *(float2*)(po + 2 * c4 + 8) = make_float2(acc[j][1][hl * 2], acc[j][1][hl * 2 + 1]);
            }
        }
    }
}

extern "C" void kernel_launch(void* const* d_in, const int* in_sizes, int n_in,
                              void* d_out, int out_size) {
    const float* in   = (const float*)d_in[0];
    const float* wgt  = (const float*)d_in[1];
    const float* bias = (const float*)d_in[2];
    float* out = (float*)d_out;

    static int configured = 0;
    if (!configured) {
        cudaFuncSetAttribute(conv3d_mma2_kernel,
                             cudaFuncAttributeMaxDynamicSharedMemorySize,
                             SM_TOTAL);
        configured = 1;
    }

    dim3 grid(4022, 2);
    conv3d_mma2_kernel<<<grid, TPB, SM_TOTAL>>>(in, wgt, bias, out);
}

// round 11
// speedup vs baseline: 3.7017x; 1.1466x over previous
#include <cuda_runtime.h>

// AbstractConv3D: 16 levels, dense R^3 grids, 3x3x3 conv, Cin=Cout=16, B=2.
// R10: mma.sync m16n8k8 tf32, 8x8x8 tile, 10^3 halo in smem, 256 thr,
// one d-plane/warp. NEW: A-row register reuse — per (kd,kw) load the 10
// distinct h-rows once per ci-region (20 LDS.64), feed all 3 kh taps from
// registers. LDS.64 per warp-tile: 540 -> 288.

#define NLEV 16
#define TPB 256
#define TOTAL_N 1844282

__constant__ int c_res[NLEV]  = {16,18,20,22,24,27,30,34,38,42,47,52,58,64,72,80};
__constant__ int c_off[NLEV]  = {0,4096,9928,17928,28576,42400,62083,89083,128387,
                                 183259,257347,361170,501778,696890,959034,1332282};
__constant__ int c_nt[NLEV]   = {2,3,3,3,3,4,4,5,5,6,6,7,8,8,9,10};   // ceil(R/8)
__constant__ int c_tblk[NLEV+1] = {0,8,35,62,89,116,180,244,369,494,710,926,
                                   1269,1781,2293,3022,4022};

// smem (bytes):
// [0,27648)   weights frag-major: [tap][f=ks*2+nh][lane][2 regs] tf32
// [27648,27712) bias f32
// [27712,98112) input tile: 2 ci-regions x 1100 granules x 32B
//   region0 = ci pairs (c,c+4) c<4 ; region1 = ci pairs (c+8,c+12)
//   granule g = dz*110 + hy*11 + wx  (10x10x10 voxels)
#define SM_W    0
#define SM_BIAS 27648
#define SM_A    27712
#define SM_REG2 35200
#define SM_TOTAL 98112

__device__ __forceinline__ unsigned smem_u32(const void* p) {
    unsigned a;
    asm("{ .reg .u64 t; cvta.to.shared.u64 t, %1; cvt.u32.u64 %0, t; }"
        : "=r"(a) : "l"(p));
    return a;
}
__device__ __forceinline__ unsigned f2tf32(float x) {
    unsigned u;
    asm("cvt.rna.tf32.f32 %0, %1;" : "=r"(u) : "f"(x));
    return u;
}
__device__ __forceinline__ uint2 lds64(unsigned a) {
    uint2 v;
    asm volatile("ld.shared.v2.b32 {%0,%1}, [%2];" : "=r"(v.x), "=r"(v.y) : "r"(a));
    return v;
}
__device__ __forceinline__ void mma_tf32(float* c,
                                         unsigned a0, unsigned a1, unsigned a2, unsigned a3,
                                         unsigned b0, unsigned b1) {
    asm volatile(
        "mma.sync.aligned.m16n8k8.row.col.f32.tf32.tf32.f32 "
        "{%0,%1,%2,%3}, {%4,%5,%6,%7}, {%8,%9}, {%0,%1,%2,%3};"
        : "+f"(c[0]), "+f"(c[1]), "+f"(c[2]), "+f"(c[3])
        : "r"(a0), "r"(a1), "r"(a2), "r"(a3), "r"(b0), "r"(b1));
}

__global__ __launch_bounds__(TPB, 2)
void conv3d_mma3_kernel(const float* __restrict__ in,
                        const float* __restrict__ wgt,
                        const float* __restrict__ bias,
                        float* __restrict__ out) {
    extern __shared__ char smem[];
    const unsigned sbase = smem_u32(smem);
    const int tid = threadIdx.x;
    const int wid = tid >> 5;      // warp = d-plane (0..7)
    const int lane = tid & 31;
    const int r4 = lane >> 2;      // w index / B co row (0..7)
    const int c4 = lane & 3;       // k-group (0..3)
    const int b = blockIdx.y;
    const int blk = blockIdx.x;

    // level + tile decode
    int l = 0;
#pragma unroll
    for (int i = 1; i < NLEV; i++)
        if (blk >= c_tblk[i]) l = i;
    const int lblk = blk - c_tblk[l];
    const int R = c_res[l];
    const int off = c_off[l];
    const int nt = c_nt[l];
    const int tz = lblk / (nt * nt);
    const int trem = lblk - tz * nt * nt;
    const int ty = trem / nt;
    const int tx = trem - ty * nt;

    // ---- stage weights frag-major ----
    {
        const float* wl = wgt + l * 6912;
        for (int it = wid; it < 108; it += 8) {
            const int tap = it >> 2;
            const int f = it & 3;
            const int ks = f >> 1;
            const int nh = f & 1;
            const int ci = 8 * ks + c4;
            const int co = 8 * nh + r4;
            const unsigned u0 = f2tf32(__ldg(wl + tap * 256 + ci * 16 + co));
            const unsigned u1 = f2tf32(__ldg(wl + tap * 256 + (ci + 4) * 16 + co));
            asm volatile("st.shared.v2.b32 [%0], {%1,%2};"
                         :: "r"(sbase + SM_W + (unsigned)(tap * 1024 + f * 256 + lane * 8)),
                            "r"(u0), "r"(u1) : "memory");
        }
        if (tid < 16)
            *(float*)(smem + SM_BIAS + tid * 4) = bias[l * 16 + tid];
    }

    // ---- stage input tile 10x10x10 (tf32, halo zero, paired-chunk layout) ----
    {
        const int d0 = tz * 8 - 1, h0 = ty * 8 - 1, w0 = tx * 8 - 1;
        const float* inB = in + ((size_t)b * TOTAL_N + off) * 16;
        for (int i = tid; i < 1000; i += TPB) {
            int dz = i / 100; int r = i - dz * 100;
            int hy = r / 10;  int wx = r - hy * 10;
            int dd = d0 + dz, hh = h0 + hy, ww = w0 + wx;
            unsigned u[16];
#pragma unroll
            for (int q = 0; q < 16; q++) u[q] = 0u;
            if (((unsigned)dd < (unsigned)R) & ((unsigned)hh < (unsigned)R) &
                ((unsigned)ww < (unsigned)R)) {
                const float4* p = (const float4*)(inB + (size_t)((dd * R + hh) * R + ww) * 16);
#pragma unroll
                for (int q = 0; q < 4; q++) {
                    float4 v = __ldg(p + q);
                    u[4 * q + 0] = f2tf32(v.x);
                    u[4 * q + 1] = f2tf32(v.y);
                    u[4 * q + 2] = f2tf32(v.z);
                    u[4 * q + 3] = f2tf32(v.w);
                }
            }
            const unsigned g32 = sbase + SM_A + (unsigned)(dz * 110 + hy * 11 + wx) * 32;
            asm volatile("st.shared.v4.b32 [%0], {%1,%2,%3,%4};"
                         :: "r"(g32), "r"(u[0]), "r"(u[4]), "r"(u[1]), "r"(u[5]) : "memory");
            asm volatile("st.shared.v4.b32 [%0], {%1,%2,%3,%4};"
                         :: "r"(g32 + 16), "r"(u[2]), "r"(u[6]), "r"(u[3]), "r"(u[7]) : "memory");
            asm volatile("st.shared.v4.b32 [%0], {%1,%2,%3,%4};"
                         :: "r"(g32 + SM_REG2), "r"(u[8]), "r"(u[12]), "r"(u[9]), "r"(u[13]) : "memory");
            asm volatile("st.shared.v4.b32 [%0], {%1,%2,%3,%4};"
                         :: "r"(g32 + SM_REG2 + 16), "r"(u[10]), "r"(u[14]), "r"(u[11]), "r"(u[15]) : "memory");
        }
    }
    __syncthreads();

    // ---- accumulators [h-pair j][nh][4], bias-initialized ----
    float acc[4][2][4];
    {
        const float* bs = (const float*)(smem + SM_BIAS);
        float b00 = bs[2 * c4], b01 = bs[2 * c4 + 1];
        float b10 = bs[2 * c4 + 8], b11 = bs[2 * c4 + 9];
#pragma unroll
        for (int j = 0; j < 4; j++) {
            acc[j][0][0] = b00; acc[j][0][1] = b01; acc[j][0][2] = b00; acc[j][0][3] = b01;
            acc[j][1][0] = b10; acc[j][1][1] = b11; acc[j][1][2] = b10; acc[j][1][3] = b11;
        }
    }

    const unsigned aBase = sbase + SM_A + (unsigned)(r4 * 32 + c4 * 8);
    const unsigned wB = sbase + SM_W + (unsigned)(lane * 8);

    for (int kd = 0; kd < 3; kd++) {
        const unsigned gkd = aBase + (unsigned)((wid + kd) * 110) * 32;
#pragma unroll
        for (int kw = 0; kw < 3; kw++) {
            const unsigned gb = gkd + (unsigned)(kw * 32);
            // load the 10 distinct h-rows for both ci-regions (20 LDS.64)
            uint2 rowA[10], rowE[10];
#pragma unroll
            for (int r = 0; r < 10; r++) {
                rowA[r] = lds64(gb + (unsigned)(r * 352));
                rowE[r] = lds64(gb + (unsigned)(r * 352) + SM_REG2);
            }
#pragma unroll
            for (int kh = 0; kh < 3; kh++) {
                const unsigned wt = wB + (unsigned)((kd * 9 + kh * 3 + kw) * 1024);
                const uint2 wb0 = lds64(wt);          // ks0 nh0
                const uint2 wb1 = lds64(wt + 256);    // ks0 nh1
                const uint2 wb2 = lds64(wt + 512);    // ks1 nh0
                const uint2 wb3 = lds64(wt + 768);    // ks1 nh1
#pragma unroll
                for (int j = 0; j < 4; j++) {
                    const int h = 2 * j + kh;
                    mma_tf32(acc[j][0], rowA[h].x, rowA[h + 1].x, rowA[h].y, rowA[h + 1].y,
                             wb0.x, wb0.y);
                    mma_tf32(acc[j][1], rowA[h].x, rowA[h + 1].x, rowA[h].y, rowA[h + 1].y,
                             wb1.x, wb1.y);
                    mma_tf32(acc[j][0], rowE[h].x, rowE[h + 1].x, rowE[h].y, rowE[h + 1].y,
                             wb2.x, wb2.y);
                    mma_tf32(acc[j][1], rowE[h].x, rowE[h + 1].x, rowE[h].y, rowE[h + 1].y,
                             wb3.x, wb3.y);
                }
            }
        }
    }

    // ---- epilogue ----
    const int ow = tx * 8 + r4;
    const int od = tz * 8 + wid;
    float* outB = out + ((size_t)b * TOTAL_N + off) * 16;
    if (ow < R && od < R) {
#pragma unroll
        for (int j = 0; j < 4; j++) {
#pragma unroll
            for (int hl = 0; hl < 2; hl++) {
                const int oh = ty * 8 + j * 2 + hl;
                if (oh >= R) continue;
                float* po = outB + (size_t)((od * R + oh) * R + ow) * 16;
                *(float2*)(po + 2 * c4)     = make_float2(acc[j][0][hl * 2], acc[j][0][hl * 2 + 1]);
                *(float2*)(po + 2 * c4 + 8) = make_float2(acc[j][1][hl * 2], acc[j][1][hl * 2 + 1]);
            }
        }
    }
}

extern "C" void kernel_launch(void* const* d_in, const int* in_sizes, int n_in,
                              void* d_out, int out_size) {
    const float* in   = (const float*)d_in[0];
    const float* wgt  = (const float*)d_in[1];
    const float* bias = (const float*)d_in[2];
    float* out = (float*)d_out;

    static int configured = 0;
    if (!configured) {
        cudaFuncSetAttribute(conv3d_mma3_kernel,
                             cudaFuncAttributeMaxDynamicSharedMemorySize,
                             SM_TOTAL);
        configured = 1;
    }

    dim3 grid(4022, 2);
    conv3d_mma3_kernel<<<grid, TPB, SM_TOTAL>>>(in, wgt, bias, out);
}

// round 12
// speedup vs baseline: 6.5079x; 1.7581x over previous
#include <cuda_runtime.h>
#include <cuda_fp16.h>

// AbstractConv3D: 16 levels, dense R^3 grids, 3x3x3 conv, Cin=Cout=16, B=2.
// R12: fp16 m16n8k16 MMA (same 10-bit mantissa as tf32, f32 accum).
// 8x8x8 tile, 10^3 halo in smem as fp16 (32B/voxel granule, ci chunk order
// (2c,2c+1,2c+8,2c+9) -> one LDS.64 per h-row = A-frag halves).
// One d-plane per warp, A-row register reuse across kh. 49KB smem -> 3 CTAs/SM.

#define NLEV 16
#define TPB 256
#define TOTAL_N 1844282

__constant__ int c_res[NLEV]  = {16,18,20,22,24,27,30,34,38,42,47,52,58,64,72,80};
__constant__ int c_off[NLEV]  = {0,4096,9928,17928,28576,42400,62083,89083,128387,
                                 183259,257347,361170,501778,696890,959034,1332282};
__constant__ int c_nt[NLEV]   = {2,3,3,3,3,4,4,5,5,6,6,7,8,8,9,10};   // ceil(R/8)
__constant__ int c_tblk[NLEV+1] = {0,8,35,62,89,116,180,244,369,494,710,926,
                                   1269,1781,2293,3022,4022};

// smem (bytes):
// [0,13824)      weights frag-major fp16: [(tap*2+nh)][lane][b0,b1] = 54*256
// [13824,13888)  bias f32
// [13888,49088)  input tile fp16: 1100 granules x 32B
//   granule g = dz*110 + hy*11 + wx ; chunk c4 = f16{2c4,2c4+1,2c4+8,2c4+9}
#define SM_W    0
#define SM_BIAS 13824
#define SM_A    13888
#define SM_TOTAL 49088

__device__ __forceinline__ unsigned smem_u32(const void* p) {
    unsigned a;
    asm("{ .reg .u64 t; cvta.to.shared.u64 t, %1; cvt.u32.u64 %0, t; }"
        : "=r"(a) : "l"(p));
    return a;
}
__device__ __forceinline__ unsigned packh2(float lo, float hi) {
    __half2 h = __floats2half2_rn(lo, hi);
    return *(unsigned*)&h;
}
__device__ __forceinline__ uint2 lds64(unsigned a) {
    uint2 v;
    asm volatile("ld.shared.v2.b32 {%0,%1}, [%2];" : "=r"(v.x), "=r"(v.y) : "r"(a));
    return v;
}
__device__ __forceinline__ void mma_f16(float* c,
                                        unsigned a0, unsigned a1, unsigned a2, unsigned a3,
                                        unsigned b0, unsigned b1) {
    asm volatile(
        "mma.sync.aligned.m16n8k16.row.col.f32.f16.f16.f32 "
        "{%0,%1,%2,%3}, {%4,%5,%6,%7}, {%8,%9}, {%0,%1,%2,%3};"
        : "+f"(c[0]), "+f"(c[1]), "+f"(c[2]), "+f"(c[3])
        : "r"(a0), "r"(a1), "r"(a2), "r"(a3), "r"(b0), "r"(b1));
}

__global__ __launch_bounds__(TPB, 3)
void conv3d_f16_kernel(const float* __restrict__ in,
                       const float* __restrict__ wgt,
                       const float* __restrict__ bias,
                       float* __restrict__ out) {
    extern __shared__ char smem[];
    const unsigned sbase = smem_u32(smem);
    const int tid = threadIdx.x;
    const int wid = tid >> 5;      // warp = d-plane (0..7)
    const int lane = tid & 31;
    const int r4 = lane >> 2;      // w index / co row (0..7)
    const int c4 = lane & 3;       // k-group (0..3)
    const int b = blockIdx.y;
    const int blk = blockIdx.x;

    // level + tile decode
    int l = 0;
#pragma unroll
    for (int i = 1; i < NLEV; i++)
        if (blk >= c_tblk[i]) l = i;
    const int lblk = blk - c_tblk[l];
    const int R = c_res[l];
    const int off = c_off[l];
    const int nt = c_nt[l];
    const int tz = lblk / (nt * nt);
    const int trem = lblk - tz * nt * nt;
    const int ty = trem / nt;
    const int tx = trem - ty * nt;

    // ---- stage weights frag-major (fp16) ----
    // item (tap, nh): lane holds b0 = (ci 2c4,2c4+1 ; co 8nh+r4), b1 = (ci +8)
    {
        const float* wl = wgt + l * 6912;
        for (int it = wid; it < 54; it += 8) {
            const int tap = it >> 1;
            const int nh = it & 1;
            const int ci0 = 2 * c4;
            const int co = 8 * nh + r4;
            const float* wp = wl + tap * 256 + co;
            const unsigned b0 = packh2(__ldg(wp + ci0 * 16), __ldg(wp + (ci0 + 1) * 16));
            const unsigned b1 = packh2(__ldg(wp + (ci0 + 8) * 16), __ldg(wp + (ci0 + 9) * 16));
            asm volatile("st.shared.v2.b32 [%0], {%1,%2};"
                         :: "r"(sbase + SM_W + (unsigned)(it * 256 + lane * 8)),
                            "r"(b0), "r"(b1) : "memory");
        }
        if (tid < 16)
            *(float*)(smem + SM_BIAS + tid * 4) = bias[l * 16 + tid];
    }

    // ---- stage input tile 10x10x10 (fp16, halo zero) ----
    {
        const int d0 = tz * 8 - 1, h0 = ty * 8 - 1, w0 = tx * 8 - 1;
        const float* inB = in + ((size_t)b * TOTAL_N + off) * 16;
        for (int i = tid; i < 1000; i += TPB) {
            int dz = i / 100; int r = i - dz * 100;
            int hy = r / 10;  int wx = r - hy * 10;
            int dd = d0 + dz, hh = h0 + hy, ww = w0 + wx;
            unsigned p[8];
#pragma unroll
            for (int q = 0; q < 8; q++) p[q] = 0u;
            if (((unsigned)dd < (unsigned)R) & ((unsigned)hh < (unsigned)R) &
                ((unsigned)ww < (unsigned)R)) {
                const float4* pg = (const float4*)(inB + (size_t)((dd * R + hh) * R + ww) * 16);
                float f[16];
#pragma unroll
                for (int q = 0; q < 4; q++)
                    *(float4*)&f[4 * q] = __ldg(pg + q);
#pragma unroll
                for (int c = 0; c < 4; c++) {
                    p[2 * c]     = packh2(f[2 * c], f[2 * c + 1]);
                    p[2 * c + 1] = packh2(f[2 * c + 8], f[2 * c + 9]);
                }
            }
            const unsigned g32 = sbase + SM_A + (unsigned)(dz * 110 + hy * 11 + wx) * 32;
            asm volatile("st.shared.v4.b32 [%0], {%1,%2,%3,%4};"
                         :: "r"(g32), "r"(p[0]), "r"(p[1]), "r"(p[2]), "r"(p[3]) : "memory");
            asm volatile("st.shared.v4.b32 [%0], {%1,%2,%3,%4};"
                         :: "r"(g32 + 16), "r"(p[4]), "r"(p[5]), "r"(p[6]), "r"(p[7]) : "memory");
        }
    }
    __syncthreads();

    // ---- accumulators [h-pair j][nh][4], bias-initialized ----
    float acc[4][2][4];
    {
        const float* bs = (const float*)(smem + SM_BIAS);
        float b00 = bs[2 * c4], b01 = bs[2 * c4 + 1];
        float b10 = bs[2 * c4 + 8], b11 = bs[2 * c4 + 9];
#pragma unroll
        for (int j = 0; j < 4; j++) {
            acc[j][0][0] = b00; acc[j][0][1] = b01; acc[j][0][2] = b00; acc[j][0][3] = b01;
            acc[j][1][0] = b10; acc[j][1][1] = b11; acc[j][1][2] = b10; acc[j][1][3] = b11;
        }
    }

    const unsigned aBase = sbase + SM_A + (unsigned)(r4 * 32 + c4 * 8);
    const unsigned wB = sbase + SM_W + (unsigned)(lane * 8);

    for (int kd = 0; kd < 3; kd++) {
        const unsigned gkd = aBase + (unsigned)((wid + kd) * 110) * 32;
#pragma unroll
        for (int kw = 0; kw < 3; kw++) {
            const unsigned gb = gkd + (unsigned)(kw * 32);
            // 10 distinct h-rows, one LDS.64 each: (a0a2 lo/hi of this h-row)
            uint2 rowF[10];
#pragma unroll
            for (int r = 0; r < 10; r++)
                rowF[r] = lds64(gb + (unsigned)(r * 352));
#pragma unroll
            for (int kh = 0; kh < 3; kh++) {
                const unsigned wt = wB + (unsigned)((kd * 9 + kh * 3 + kw) * 512);
                const uint2 wb0 = lds64(wt);          // nh0 (b0,b1)
                const uint2 wb1 = lds64(wt + 256);    // nh1
#pragma unroll
                for (int j = 0; j < 4; j++) {
                    const int h = 2 * j + kh;
                    mma_f16(acc[j][0], rowF[h].x, rowF[h + 1].x, rowF[h].y, rowF[h + 1].y,
                            wb0.x, wb0.y);
                    mma_f16(acc[j][1], rowF[h].x, rowF[h + 1].x, rowF[h].y, rowF[h + 1].y,
                            wb1.x, wb1.y);
                }
            }
        }
    }

    // ---- epilogue ----
    const int ow = tx * 8 + r4;
    const int od = tz * 8 + wid;
    float* outB = out + ((size_t)b * TOTAL_N + off) * 16;
    if (ow < R && od < R) {
#pragma unroll
        for (int j = 0; j < 4; j++) {
#pragma unroll
            for (int hl = 0; hl < 2; hl++) {
                const int oh = ty * 8 + j * 2 + hl;
                if (oh >= R) continue;
                float* po = outB + (size_t)((od * R + oh) * R + ow) * 16;
                *(float2*)(po + 2 * c4)     = make_float2(acc[j][0][hl * 2], acc[j][0][hl * 2 + 1]);
                *(float2*)(po + 2 * c4 + 8) = make_float2(acc[j][1][hl * 2], acc[j][1][hl * 2 + 1]);
            }
        }
    }
}

extern "C" void kernel_launch(void* const* d_in, const int* in_sizes, int n_in,
                              void* d_out, int out_size) {
    const float* in   = (const float*)d_in[0];
    const float* wgt  = (const float*)d_in[1];
    const float* bias = (const float*)d_in[2];
    float* out = (float*)d_out;

    static int configured = 0;
    if (!configured) {
        cudaFuncSetAttribute(conv3d_f16_kernel,
                             cudaFuncAttributeMaxDynamicSharedMemorySize,
                             SM_TOTAL);
        configured = 1;
    }

    dim3 grid(4022, 2);
    conv3d_f16_kernel<<<grid, TPB, SM_TOTAL>>>(in, wgt, bias, out);
}